// round 1
// baseline (speedup 1.0000x reference)
#include <cuda_runtime.h>
#include <math.h>

// Problem constants (fixed by the reference)
#define B_ROWS 16384
#define DIM    768
#define NP     8192
#define TOPK   5

// GEMM tiling
#define BM 128
#define BN 128
#define BK 16
#define TM 8
#define TN 8
#define NTHREADS 256
#define SC_STRIDE (BN + 1)   // 129 -> conflict-free column access

// smem layout (floats):
//  As[2][BK][BM]  = 2*16*128 = 4096
//  Bs[2][BK][BN]  = 4096
//  sc[BM][129]    = 16512
//  bs[BN]         = 128
// total floats = 24832 -> 99328 bytes dynamic smem
#define SMEM_FLOATS (2*BK*BM + 2*BK*BN + BM*SC_STRIDE + BN)

__global__ __launch_bounds__(NTHREADS, 1)
void topk_prompt_fused_kernel(const float* __restrict__ V,
                              const float* __restrict__ W,
                              const float* __restrict__ bias,
                              const float* __restrict__ pool,
                              float* __restrict__ out)
{
    extern __shared__ float smem[];
    float* As = smem;                       // [2][BK][BM]
    float* Bs = As + 2 * BK * BM;           // [2][BK][BN]
    float* sc = Bs + 2 * BK * BN;           // [BM][SC_STRIDE]
    float* bs = sc + BM * SC_STRIDE;        // [BN]

    const int tid  = threadIdx.x;
    const int row0 = blockIdx.x * BM;

    const int trow = (tid >> 4) * TM;       // 0..120
    const int tcol = (tid & 15) * TN;       // 0..120

    // global-load mapping: each thread loads 2 float4 per matrix per k-tile
    const int la_r = tid >> 2;              // 0..63
    const int la_k = (tid & 3) * 4;         // 0,4,8,12

    // per-row top-5 (threads 0..127 own row = tid), sorted descending
    float ts0 = -INFINITY, ts1 = -INFINITY, ts2 = -INFINITY,
          ts3 = -INFINITY, ts4 = -INFINITY;
    int   ti0 = 0, ti1 = 0, ti2 = 0, ti3 = 0, ti4 = 0;

    const int nK = DIM / BK;                // 48

    for (int nt = 0; nt < NP / BN; ++nt) {
        const int n0 = nt * BN;

        __syncthreads();   // prior tile's scan (reads sc, bs) complete

        if (tid < BN) bs[tid] = bias[n0 + tid];

        float acc[TM][TN];
        #pragma unroll
        for (int i = 0; i < TM; ++i)
            #pragma unroll
            for (int j = 0; j < TN; ++j)
                acc[i][j] = 0.0f;

        // -------- fp32 GEMM: acc = V[rows, :] * W[n0:n0+BN, :]^T --------
        float4 ra0, ra1, rb0, rb1;

        // preload k-tile 0
        {
            const int k0 = 0;
            ra0 = *(const float4*)&V[(size_t)(row0 + la_r)      * DIM + k0 + la_k];
            ra1 = *(const float4*)&V[(size_t)(row0 + la_r + 64) * DIM + k0 + la_k];
            rb0 = *(const float4*)&W[(size_t)(n0  + la_r)       * DIM + k0 + la_k];
            rb1 = *(const float4*)&W[(size_t)(n0  + la_r + 64)  * DIM + k0 + la_k];
        }
        {
            float* a0 = As;                 // buffer 0
            float* b0 = Bs;
            #pragma unroll
            for (int q = 0; q < 4; ++q) {
                a0[(la_k + q) * BM + la_r]      = (&ra0.x)[q];
                a0[(la_k + q) * BM + la_r + 64] = (&ra1.x)[q];
                b0[(la_k + q) * BN + la_r]      = (&rb0.x)[q];
                b0[(la_k + q) * BN + la_r + 64] = (&rb1.x)[q];
            }
        }
        __syncthreads();

        int buf = 0;
        for (int kt = 0; kt < nK; ++kt) {
            // prefetch next k-tile into registers
            if (kt + 1 < nK) {
                const int k0 = (kt + 1) * BK;
                ra0 = *(const float4*)&V[(size_t)(row0 + la_r)      * DIM + k0 + la_k];
                ra1 = *(const float4*)&V[(size_t)(row0 + la_r + 64) * DIM + k0 + la_k];
                rb0 = *(const float4*)&W[(size_t)(n0  + la_r)       * DIM + k0 + la_k];
                rb1 = *(const float4*)&W[(size_t)(n0  + la_r + 64)  * DIM + k0 + la_k];
            }

            // compute on buffer `buf`
            const float* a = As + buf * BK * BM;
            const float* b = Bs + buf * BK * BN;
            #pragma unroll
            for (int kk = 0; kk < BK; ++kk) {
                float af[TM], bf[TN];
                float4 t;
                t = *(const float4*)&a[kk * BM + trow];
                af[0]=t.x; af[1]=t.y; af[2]=t.z; af[3]=t.w;
                t = *(const float4*)&a[kk * BM + trow + 4];
                af[4]=t.x; af[5]=t.y; af[6]=t.z; af[7]=t.w;
                t = *(const float4*)&b[kk * BN + tcol];
                bf[0]=t.x; bf[1]=t.y; bf[2]=t.z; bf[3]=t.w;
                t = *(const float4*)&b[kk * BN + tcol + 4];
                bf[4]=t.x; bf[5]=t.y; bf[6]=t.z; bf[7]=t.w;
                #pragma unroll
                for (int i = 0; i < TM; ++i)
                    #pragma unroll
                    for (int j = 0; j < TN; ++j)
                        acc[i][j] = fmaf(af[i], bf[j], acc[i][j]);
            }

            if (kt + 1 < nK) {
                __syncthreads();   // all reads of the other buffer are long done;
                                   // this guards reads of `buf` vs NEXT store? No:
                                   // it guards: everyone finished reading buf^1 two
                                   // iters ago; here it ensures all compute reads of
                                   // the buffer we are about to overwrite are done.
                float* a1 = As + (buf ^ 1) * BK * BM;
                float* b1 = Bs + (buf ^ 1) * BK * BN;
                #pragma unroll
                for (int q = 0; q < 4; ++q) {
                    a1[(la_k + q) * BM + la_r]      = (&ra0.x)[q];
                    a1[(la_k + q) * BM + la_r + 64] = (&ra1.x)[q];
                    b1[(la_k + q) * BN + la_r]      = (&rb0.x)[q];
                    b1[(la_k + q) * BN + la_r + 64] = (&rb1.x)[q];
                }
                __syncthreads();
                buf ^= 1;
            }
        }

        // -------- stage score tile to smem --------
        __syncthreads();   // previous-tile scan finished (loop-top sync) AND all
                           // compute done; safe to write sc
        #pragma unroll
        for (int i = 0; i < TM; ++i)
            #pragma unroll
            for (int j = 0; j < TN; ++j)
                sc[(trow + i) * SC_STRIDE + tcol + j] = acc[i][j];
        __syncthreads();

        // -------- per-row top-5 update (threads 0..127, row = tid) --------
        if (tid < BM) {
            const float* srow = &sc[tid * SC_STRIDE];
            #pragma unroll 4
            for (int c = 0; c < BN; ++c) {
                float v = srow[c] + bs[c];
                int   n = n0 + c;
                if (v > ts4) {
                    if (v > ts2) {
                        if (v > ts1) {
                            if (v > ts0) {
                                ts4=ts3; ti4=ti3; ts3=ts2; ti3=ti2;
                                ts2=ts1; ti2=ti1; ts1=ts0; ti1=ti0;
                                ts0=v;   ti0=n;
                            } else {
                                ts4=ts3; ti4=ti3; ts3=ts2; ti3=ti2;
                                ts2=ts1; ti2=ti1; ts1=v;   ti1=n;
                            }
                        } else {
                            ts4=ts3; ti4=ti3; ts3=ts2; ti3=ti2;
                            ts2=v;   ti2=n;
                        }
                    } else {
                        if (v > ts3) {
                            ts4=ts3; ti4=ti3; ts3=v; ti3=n;
                        } else {
                            ts4=v; ti4=n;
                        }
                    }
                }
            }
        }
    }

    // -------- softmax over top-5, publish to smem --------
    __syncthreads();                 // last scan done; sc free for reuse
    float* wsm = sc;                 // [BM][5] weights
    int*   ism = (int*)(sc + BM * 8); // [BM][5] indices (offset keeps regions apart)
    if (tid < BM) {
        float m  = ts0;              // ts0 is the max
        float e0 = expf(ts0 - m), e1 = expf(ts1 - m), e2 = expf(ts2 - m),
              e3 = expf(ts3 - m), e4 = expf(ts4 - m);
        float inv = 1.0f / (e0 + e1 + e2 + e3 + e4);
        wsm[tid * 5 + 0] = e0 * inv;  ism[tid * 5 + 0] = ti0;
        wsm[tid * 5 + 1] = e1 * inv;  ism[tid * 5 + 1] = ti1;
        wsm[tid * 5 + 2] = e2 * inv;  ism[tid * 5 + 2] = ti2;
        wsm[tid * 5 + 3] = e3 * inv;  ism[tid * 5 + 3] = ti3;
        wsm[tid * 5 + 4] = e4 * inv;  ism[tid * 5 + 4] = ti4;
    }
    __syncthreads();

    // -------- weighted gather-combine: out[r] = sum_k w_k * pool[idx_k] --------
    for (int r = 0; r < BM; ++r) {
        const float w0 = wsm[r * 5 + 0], w1 = wsm[r * 5 + 1], w2 = wsm[r * 5 + 2],
                    w3 = wsm[r * 5 + 3], w4 = wsm[r * 5 + 4];
        const size_t p0 = (size_t)ism[r * 5 + 0] * DIM;
        const size_t p1 = (size_t)ism[r * 5 + 1] * DIM;
        const size_t p2 = (size_t)ism[r * 5 + 2] * DIM;
        const size_t p3 = (size_t)ism[r * 5 + 3] * DIM;
        const size_t p4 = (size_t)ism[r * 5 + 4] * DIM;
        float* orow = &out[(size_t)(row0 + r) * DIM];
        for (int d = tid; d < DIM; d += NTHREADS) {
            float o = w0 * pool[p0 + d];
            o = fmaf(w1, pool[p1 + d], o);
            o = fmaf(w2, pool[p2 + d], o);
            o = fmaf(w3, pool[p3 + d], o);
            o = fmaf(w4, pool[p4 + d], o);
            orow[d] = o;
        }
    }
}

extern "C" void kernel_launch(void* const* d_in, const int* in_sizes, int n_in,
                              void* d_out, int out_size)
{
    const float* V    = (const float*)d_in[0];   // [16384, 768]
    const float* W    = (const float*)d_in[1];   // [8192, 768]
    const float* bias = (const float*)d_in[2];   // [8192]
    const float* pool = (const float*)d_in[3];   // [8192, 768]
    float* out = (float*)d_out;                  // [16384, 768]

    const size_t smem_bytes = (size_t)SMEM_FLOATS * sizeof(float);  // 99328
    cudaFuncSetAttribute(topk_prompt_fused_kernel,
                         cudaFuncAttributeMaxDynamicSharedMemorySize,
                         (int)smem_bytes);

    topk_prompt_fused_kernel<<<B_ROWS / BM, NTHREADS, smem_bytes>>>(
        V, W, bias, pool, out);
}

// round 4
// speedup vs baseline: 3.0182x; 3.0182x over previous
#include <cuda_runtime.h>
#include <cuda_bf16.h>
#include <math.h>
#include <stdint.h>

// ---------------- problem constants ----------------
#define B_ROWS 16384
#define DIM    768
#define NP     8192
#define NCAND  16
#define SCOFF  3.0f

// ---------------- GEMM tiling ----------------
#define BM 128
#define BN 256
#define BK 32
#define NSTAGE 4
#define NT_TILES (NP / BN)        // 32
#define KCH      (DIM / BK)       // 24
#define NCHUNK   (NT_TILES * KCH) // 768
#define APITCH   40               // bf16 elems per smem row (80B, conflict-free)
#define A_STAGE_B (BM * APITCH * 2)            // 10240
#define B_STAGE_B (BN * APITCH * 2)            // 20480
#define STAGE_BYTES (A_STAGE_B + B_STAGE_B)    // 30720
#define SC_STRIDE 264             // bf16 elems per sc row

// smem layout (bytes)
#define SM_STG   0
#define SM_SC    (NSTAGE * STAGE_BYTES)              // 122880
#define SM_BIAS  (SM_SC + BM * SC_STRIDE * 2)        // 190464
#define SM_TSV   (SM_BIAS + BN * 4)                  // 191488
#define SM_TSI   (SM_TSV + BM * NCAND * 4)           // 199680
#define SM_TOTAL (SM_TSI + BM * NCAND * 4)           // 207872

// ---------------- device scratch (static allocs are allowed) ----------------
__device__ __nv_bfloat16 g_V16[(size_t)B_ROWS * DIM];
__device__ __nv_bfloat16 g_W16[(size_t)NP * DIM];
__device__ int           g_cand[(size_t)B_ROWS * NCAND];

// ---------------- helpers ----------------
static __device__ __forceinline__ uint32_t s2u(const void* p){
    uint32_t a;
    asm("{ .reg .u64 t; cvta.to.shared.u64 t, %1; cvt.u32.u64 %0, t; }"
        : "=r"(a) : "l"(p));
    return a;
}
static __device__ __forceinline__ void cpa16(uint32_t dst, const void* src){
    asm volatile("cp.async.cg.shared.global [%0], [%1], 16;"
        :: "r"(dst), "l"(src) : "memory");
}
#define CPA_COMMIT() asm volatile("cp.async.commit_group;" ::: "memory")
#define CPA_WAIT2()  asm volatile("cp.async.wait_group 2;" ::: "memory")

static __device__ __forceinline__ void mma16816(float* d, const uint32_t* a,
                                                uint32_t b0, uint32_t b1){
    asm volatile(
        "mma.sync.aligned.m16n8k16.row.col.f32.bf16.bf16.f32 "
        "{%0,%1,%2,%3}, {%4,%5,%6,%7}, {%8,%9}, {%0,%1,%2,%3};"
        : "+f"(d[0]), "+f"(d[1]), "+f"(d[2]), "+f"(d[3])
        : "r"(a[0]), "r"(a[1]), "r"(a[2]), "r"(a[3]), "r"(b0), "r"(b1));
}

// ---------------- kernel 1: fp32 -> bf16 convert ----------------
__global__ void convert_kernel(const float* __restrict__ V,
                               const float* __restrict__ W)
{
    const size_t NV4 = (size_t)B_ROWS * DIM / 4;   // float4 count for V
    const size_t NW4 = (size_t)NP * DIM / 4;
    const size_t stride = (size_t)gridDim.x * blockDim.x;
    for (size_t i = blockIdx.x * (size_t)blockDim.x + threadIdx.x;
         i < NV4 + NW4; i += stride){
        if (i < NV4){
            float4 f = ((const float4*)V)[i];
            __nv_bfloat162* d = (__nv_bfloat162*)g_V16 + i*2;
            d[0] = __float22bfloat162_rn(make_float2(f.x, f.y));
            d[1] = __float22bfloat162_rn(make_float2(f.z, f.w));
        } else {
            size_t j = i - NV4;
            float4 f = ((const float4*)W)[j];
            __nv_bfloat162* d = (__nv_bfloat162*)g_W16 + j*2;
            d[0] = __float22bfloat162_rn(make_float2(f.x, f.y));
            d[1] = __float22bfloat162_rn(make_float2(f.z, f.w));
        }
    }
}

// ---------------- kernel 2: bf16 mma.sync GEMM + top-16 scan ----------------
__global__ __launch_bounds__(256, 1)
void gemm_topk_kernel(const float* __restrict__ bias)
{
    extern __shared__ char smem[];
    const uint32_t sbase = s2u(smem);
    const int tid  = threadIdx.x;
    const int lane = tid & 31;
    const int wid  = tid >> 5;
    const int g    = lane >> 2;      // 0..7
    const int tq   = lane & 3;       // 0..3
    const int wm   = wid & 1;        // M half (64 rows)
    const int wn   = wid >> 1;       // N quarter (64 cols)
    const int row0 = blockIdx.x * BM;

    float* bias_s = (float*)(smem + SM_BIAS);
    float* tsv_s  = (float*)(smem + SM_TSV);
    int*   tsi_s  = (int*)(smem + SM_TSI);

    if (tid < BM){
        #pragma unroll
        for (int k = 0; k < NCAND; ++k){
            tsv_s[tid*NCAND + k] = -INFINITY;
            tsi_s[tid*NCAND + k] = 0;
        }
    }
    float thr = -INFINITY;   // per-scan-thread 16th value cache

    // issue one chunk's cp.asyncs (all 256 threads, 6 each)
    auto issue_chunk = [&](int c){
        const int nt = c / KCH;
        const int kt = c - nt * KCH;
        const uint32_t stg = sbase + (uint32_t)(c & (NSTAGE-1)) * STAGE_BYTES;
        #pragma unroll
        for (int i = 0; i < 6; ++i){
            const int op = tid + i * 256;
            if (op < 512){
                const int r  = op >> 2, kc = op & 3;
                const __nv_bfloat16* src =
                    g_V16 + (size_t)(row0 + r) * DIM + kt*BK + kc*8;
                cpa16(stg + (uint32_t)r*80u + (uint32_t)kc*16u, src);
            } else {
                const int x = op - 512;
                const int r = x >> 2, kc = x & 3;
                const __nv_bfloat16* src =
                    g_W16 + (size_t)(nt*BN + r) * DIM + kt*BK + kc*8;
                cpa16(stg + A_STAGE_B + (uint32_t)r*80u + (uint32_t)kc*16u, src);
            }
        }
        CPA_COMMIT();
    };

    // prologue: 3 chunks in flight
    issue_chunk(0); issue_chunk(1); issue_chunk(2);

    for (int nt = 0; nt < NT_TILES; ++nt){
        float acc[4][8][4];
        #pragma unroll
        for (int mi = 0; mi < 4; ++mi)
            #pragma unroll
            for (int ni = 0; ni < 8; ++ni)
                #pragma unroll
                for (int q = 0; q < 4; ++q) acc[mi][ni][q] = 0.0f;

        for (int kt = 0; kt < KCH; ++kt){
            const int c = nt * KCH + kt;
            CPA_WAIT2();
            __syncthreads();
            if (kt == 0) bias_s[tid] = bias[nt*BN + tid];   // 256 loads

            if (c + 3 < NCHUNK) issue_chunk(c + 3);
            else                CPA_COMMIT();               // empty group

            const char* stg = smem + (size_t)(c & (NSTAGE-1)) * STAGE_BYTES;
            const __nv_bfloat16* As = (const __nv_bfloat16*)stg;
            const __nv_bfloat16* Bs = (const __nv_bfloat16*)(stg + A_STAGE_B);

            #pragma unroll
            for (int ks = 0; ks < 2; ++ks){
                uint32_t a[4][4];
                #pragma unroll
                for (int mi = 0; mi < 4; ++mi){
                    const int r0 = wm*64 + mi*16;
                    const __nv_bfloat16* ap = As + ks*16 + 2*tq;
                    a[mi][0] = *(const uint32_t*)(ap + (r0+g)  *APITCH);
                    a[mi][1] = *(const uint32_t*)(ap + (r0+g+8)*APITCH);
                    a[mi][2] = *(const uint32_t*)(ap + (r0+g)  *APITCH + 8);
                    a[mi][3] = *(const uint32_t*)(ap + (r0+g+8)*APITCH + 8);
                }
                #pragma unroll
                for (int ni = 0; ni < 8; ++ni){
                    const int cb = wn*64 + ni*8;
                    const __nv_bfloat16* bp = Bs + (cb+g)*APITCH + ks*16 + 2*tq;
                    const uint32_t b0 = *(const uint32_t*)bp;
                    const uint32_t b1 = *(const uint32_t*)(bp + 8);
                    #pragma unroll
                    for (int mi = 0; mi < 4; ++mi)
                        mma16816(acc[mi][ni], a[mi], b0, b1);
                }
            }
        }

        // ---- stage scores (offset bf16, bias folded) ----
        #pragma unroll
        for (int mi = 0; mi < 4; ++mi){
            const int row = wm*64 + mi*16 + g;
            #pragma unroll
            for (int ni = 0; ni < 8; ++ni){
                const int col = wn*64 + ni*8 + 2*tq;
                const float b0 = bias_s[col]     - SCOFF;
                const float b1 = bias_s[col + 1] - SCOFF;
                __nv_bfloat162* p0 =
                    (__nv_bfloat162*)(smem + SM_SC + ((size_t)row*SC_STRIDE + col)*2);
                __nv_bfloat162* p1 =
                    (__nv_bfloat162*)(smem + SM_SC + ((size_t)(row+8)*SC_STRIDE + col)*2);
                *p0 = __float22bfloat162_rn(
                        make_float2(acc[mi][ni][0] + b0, acc[mi][ni][1] + b1));
                *p1 = __float22bfloat162_rn(
                        make_float2(acc[mi][ni][2] + b0, acc[mi][ni][3] + b1));
            }
        }
        __syncthreads();

        // ---- per-row top-16 scan (threads 0..127) ----
        if (tid < BM){
            const __nv_bfloat162* srow =
                (const __nv_bfloat162*)(smem + SM_SC + (size_t)tid*SC_STRIDE*2);
            const int base = tid * NCAND;
            const int n0   = nt * BN;
            #pragma unroll 4
            for (int j = 0; j < BN/2; ++j){
                const float2 f = __bfloat1622float2(srow[j]);
                if (f.x > thr){
                    int k = NCAND-1;
                    while (k > 0 && tsv_s[base+k-1] < f.x){
                        tsv_s[base+k] = tsv_s[base+k-1];
                        tsi_s[base+k] = tsi_s[base+k-1];
                        --k;
                    }
                    tsv_s[base+k] = f.x; tsi_s[base+k] = n0 + 2*j;
                    thr = tsv_s[base+NCAND-1];
                }
                if (f.y > thr){
                    int k = NCAND-1;
                    while (k > 0 && tsv_s[base+k-1] < f.y){
                        tsv_s[base+k] = tsv_s[base+k-1];
                        tsi_s[base+k] = tsi_s[base+k-1];
                        --k;
                    }
                    tsv_s[base+k] = f.y; tsi_s[base+k] = n0 + 2*j + 1;
                    thr = tsv_s[base+NCAND-1];
                }
            }
        }
        __syncthreads();
    }

    if (tid < BM){
        #pragma unroll
        for (int k = 0; k < NCAND; ++k)
            g_cand[(size_t)(row0 + tid)*NCAND + k] = tsi_s[tid*NCAND + k];
    }
}

// ---------------- kernel 3: exact rescore + softmax + combine ----------------
__global__ __launch_bounds__(256)
void rescore_kernel(const float* __restrict__ V,
                    const float* __restrict__ W,
                    const float* __restrict__ bias,
                    const float* __restrict__ pool,
                    float* __restrict__ out)
{
    const int lane = threadIdx.x & 31;
    const int wid  = threadIdx.x >> 5;
    const int row  = blockIdx.x * 8 + wid;

    int ids[NCAND]; float acc[NCAND];
    #pragma unroll
    for (int k = 0; k < NCAND; ++k){
        ids[k] = g_cand[(size_t)row*NCAND + k];
        acc[k] = 0.0f;
    }
    const float* vrow = V + (size_t)row * DIM;
    #pragma unroll 1
    for (int i = 0; i < DIM/32; ++i){
        const int d = i*32 + lane;
        const float v = vrow[d];
        #pragma unroll
        for (int k = 0; k < NCAND; ++k)
            acc[k] = fmaf(v, __ldg(&W[(size_t)ids[k]*DIM + d]), acc[k]);
    }
    #pragma unroll
    for (int k = 0; k < NCAND; ++k){
        #pragma unroll
        for (int off = 16; off; off >>= 1)
            acc[k] += __shfl_xor_sync(0xffffffffu, acc[k], off);
        acc[k] += bias[ids[k]];
    }
    // full descending sort (redundant across lanes; all-register)
    #pragma unroll
    for (int a = 0; a < NCAND; ++a)
        #pragma unroll
        for (int j = 0; j < NCAND-1; ++j)
            if (acc[j] < acc[j+1]){
                float tv = acc[j]; acc[j] = acc[j+1]; acc[j+1] = tv;
                int   tx = ids[j]; ids[j] = ids[j+1]; ids[j+1] = tx;
            }
    const float m = acc[0];
    float e0 = expf(acc[0]-m), e1 = expf(acc[1]-m), e2 = expf(acc[2]-m),
          e3 = expf(acc[3]-m), e4 = expf(acc[4]-m);
    const float inv = 1.0f / (e0+e1+e2+e3+e4);
    e0 *= inv; e1 *= inv; e2 *= inv; e3 *= inv; e4 *= inv;
    const float* p0 = pool + (size_t)ids[0]*DIM;
    const float* p1 = pool + (size_t)ids[1]*DIM;
    const float* p2 = pool + (size_t)ids[2]*DIM;
    const float* p3 = pool + (size_t)ids[3]*DIM;
    const float* p4 = pool + (size_t)ids[4]*DIM;
    float* orow = out + (size_t)row * DIM;
    #pragma unroll 1
    for (int i = 0; i < DIM/32; ++i){
        const int d = i*32 + lane;
        float o = e0 * p0[d];
        o = fmaf(e1, p1[d], o);
        o = fmaf(e2, p2[d], o);
        o = fmaf(e3, p3[d], o);
        o = fmaf(e4, p4[d], o);
        orow[d] = o;
    }
}

// ---------------- launch ----------------
extern "C" void kernel_launch(void* const* d_in, const int* in_sizes, int n_in,
                              void* d_out, int out_size)
{
    const float* V    = (const float*)d_in[0];   // [16384, 768]
    const float* W    = (const float*)d_in[1];   // [8192, 768]
    const float* bias = (const float*)d_in[2];   // [8192]
    const float* pool = (const float*)d_in[3];   // [8192, 768]
    float* out = (float*)d_out;

    cudaFuncSetAttribute(gemm_topk_kernel,
                         cudaFuncAttributeMaxDynamicSharedMemorySize, SM_TOTAL);

    convert_kernel<<<1184, 256>>>(V, W);
    gemm_topk_kernel<<<B_ROWS / BM, 256, SM_TOTAL>>>(bias);
    rescore_kernel<<<B_ROWS / 8, 256>>>(V, W, bias, pool, out);
}

// round 5
// speedup vs baseline: 4.2645x; 1.4129x over previous
#include <cuda_runtime.h>
#include <cuda_bf16.h>
#include <math.h>
#include <stdint.h>

// ---------------- problem constants ----------------
#define B_ROWS 16384
#define DIM    768
#define NP     8192
#define NCAND  16           // candidates per row handed to rescore
#define LDEPTH 8            // per-half-list depth (2 lists per row)
#define SCOFF  3.0f

// ---------------- GEMM tiling ----------------
#define BM 128
#define BN 256
#define BK 32
#define NSTAGE 4
#define NTHREADS 512
#define NT_TILES (NP / BN)        // 32
#define KCH      (DIM / BK)       // 24
#define NCHUNK   (NT_TILES * KCH) // 768
#define APITCH   40               // bf16 elems per smem row (80B, conflict-free)
#define A_STAGE_B (BM * APITCH * 2)            // 10240
#define B_STAGE_B (BN * APITCH * 2)            // 20480
#define STAGE_BYTES (A_STAGE_B + B_STAGE_B)    // 30720
#define SC_STRIDE 264             // bf16 elems per sc row

// smem layout (bytes)
#define SM_SC    (NSTAGE * STAGE_BYTES)              // 122880
#define SM_BIAS  (SM_SC + BM * SC_STRIDE * 2)        // 190464
#define SM_TSV   (SM_BIAS + BN * 4)                  // 191488
#define SM_TSI   (SM_TSV + 256 * LDEPTH * 4)         // 199680
#define SM_TOTAL (SM_TSI + 256 * LDEPTH * 4)         // 207872

// ---------------- device scratch ----------------
__device__ __nv_bfloat16 g_V16[(size_t)B_ROWS * DIM];
__device__ __nv_bfloat16 g_W16[(size_t)NP * DIM];
__device__ int           g_cand[(size_t)B_ROWS * NCAND];

// ---------------- helpers ----------------
static __device__ __forceinline__ uint32_t s2u(const void* p){
    uint32_t a;
    asm("{ .reg .u64 t; cvta.to.shared.u64 t, %1; cvt.u32.u64 %0, t; }"
        : "=r"(a) : "l"(p));
    return a;
}
static __device__ __forceinline__ void cpa16(uint32_t dst, const void* src){
    asm volatile("cp.async.cg.shared.global [%0], [%1], 16;"
        :: "r"(dst), "l"(src) : "memory");
}
#define CPA_COMMIT() asm volatile("cp.async.commit_group;" ::: "memory")
#define CPA_WAIT2()  asm volatile("cp.async.wait_group 2;" ::: "memory")

static __device__ __forceinline__ void ldsm4(uint32_t* r, uint32_t addr){
    asm volatile("ldmatrix.sync.aligned.m8n8.x4.shared.b16 {%0,%1,%2,%3}, [%4];"
        : "=r"(r[0]), "=r"(r[1]), "=r"(r[2]), "=r"(r[3]) : "r"(addr));
}
static __device__ __forceinline__ void mma16816(float* d, const uint32_t* a,
                                                uint32_t b0, uint32_t b1){
    asm volatile(
        "mma.sync.aligned.m16n8k16.row.col.f32.bf16.bf16.f32 "
        "{%0,%1,%2,%3}, {%4,%5,%6,%7}, {%8,%9}, {%0,%1,%2,%3};"
        : "+f"(d[0]), "+f"(d[1]), "+f"(d[2]), "+f"(d[3])
        : "r"(a[0]), "r"(a[1]), "r"(a[2]), "r"(a[3]), "r"(b0), "r"(b1));
}

// ---------------- kernel 1: fp32 -> bf16 convert ----------------
__global__ void convert_kernel(const float* __restrict__ V,
                               const float* __restrict__ W)
{
    const size_t NV4 = (size_t)B_ROWS * DIM / 4;
    const size_t NW4 = (size_t)NP * DIM / 4;
    const size_t stride = (size_t)gridDim.x * blockDim.x;
    for (size_t i = blockIdx.x * (size_t)blockDim.x + threadIdx.x;
         i < NV4 + NW4; i += stride){
        if (i < NV4){
            float4 f = ((const float4*)V)[i];
            __nv_bfloat162* d = (__nv_bfloat162*)g_V16 + i*2;
            d[0] = __float22bfloat162_rn(make_float2(f.x, f.y));
            d[1] = __float22bfloat162_rn(make_float2(f.z, f.w));
        } else {
            size_t j = i - NV4;
            float4 f = ((const float4*)W)[j];
            __nv_bfloat162* d = (__nv_bfloat162*)g_W16 + j*2;
            d[0] = __float22bfloat162_rn(make_float2(f.x, f.y));
            d[1] = __float22bfloat162_rn(make_float2(f.z, f.w));
        }
    }
}

// ---------------- kernel 2: bf16 mma.sync GEMM + top-k scan ----------------
__global__ __launch_bounds__(NTHREADS, 1)
void gemm_topk_kernel(const float* __restrict__ bias)
{
    extern __shared__ char smem[];
    const uint32_t sbase = s2u(smem);
    const int tid  = threadIdx.x;
    const int lane = tid & 31;
    const int wid  = tid >> 5;
    const int g    = lane >> 2;      // 0..7
    const int tq   = lane & 3;       // 0..3
    const int wm   = wid & 1;        // M half (64 rows)
    const int wn   = wid >> 1;       // N eighth (32 cols)
    const int row0 = blockIdx.x * BM;

    float* bias_s = (float*)(smem + SM_BIAS);
    float* tsv_s  = (float*)(smem + SM_TSV);
    int*   tsi_s  = (int*)(smem + SM_TSI);

    if (tid < 256){
        #pragma unroll
        for (int k = 0; k < LDEPTH; ++k){
            tsv_s[tid*LDEPTH + k] = -INFINITY;
            tsi_s[tid*LDEPTH + k] = 0;
        }
    }
    float thr = -INFINITY;

    // per-lane ldmatrix row/khalf decomposition (see fragment mapping)
    const uint32_t a_row = (uint32_t)(wm*64 + (lane & 15));        // + mi*16
    const uint32_t a_kb  = (uint32_t)((lane >> 4) * 16);           // k-half bytes
    const uint32_t b_row = (uint32_t)(wn*32 + (lane & 7) + ((lane & 16) >> 1)); // + nip*16
    const uint32_t b_kb  = (uint32_t)(((lane >> 3) & 1) * 16);

    // issue one chunk's cp.asyncs (512 threads, 3 x 16B each)
    auto issue_chunk = [&](int c){
        const int nt = c / KCH;
        const int kt = c - nt * KCH;
        const uint32_t stg = sbase + (uint32_t)(c & (NSTAGE-1)) * STAGE_BYTES;
        {   // A: ops 0..511
            const int r = tid >> 2, kc = tid & 3;
            const __nv_bfloat16* src = g_V16 + (size_t)(row0 + r)*DIM + kt*BK + kc*8;
            cpa16(stg + (uint32_t)r*80u + (uint32_t)kc*16u, src);
        }
        #pragma unroll
        for (int i = 0; i < 2; ++i){   // B: ops 512..1535
            const int x = tid + i*512;
            const int r = x >> 2, kc = x & 3;
            const __nv_bfloat16* src = g_W16 + (size_t)(nt*BN + r)*DIM + kt*BK + kc*8;
            cpa16(stg + A_STAGE_B + (uint32_t)r*80u + (uint32_t)kc*16u, src);
        }
        CPA_COMMIT();
    };

    issue_chunk(0); issue_chunk(1); issue_chunk(2);

    for (int nt = 0; nt < NT_TILES; ++nt){
        float acc[4][4][4];   // [mi][ni][q]  warp tile 64x32
        #pragma unroll
        for (int mi = 0; mi < 4; ++mi)
            #pragma unroll
            for (int ni = 0; ni < 4; ++ni)
                #pragma unroll
                for (int q = 0; q < 4; ++q) acc[mi][ni][q] = 0.0f;

        #pragma unroll 1
        for (int kt = 0; kt < KCH; ++kt){
            const int c = nt * KCH + kt;
            CPA_WAIT2();
            __syncthreads();
            if (kt == 0 && tid < 256) bias_s[tid] = bias[nt*BN + tid];

            if (c + 3 < NCHUNK) issue_chunk(c + 3);
            else                CPA_COMMIT();

            const uint32_t stg  = sbase + (uint32_t)(c & (NSTAGE-1)) * STAGE_BYTES;
            const uint32_t stgB = stg + A_STAGE_B;

            #pragma unroll
            for (int ks = 0; ks < 2; ++ks){
                uint32_t a[4][4], b[4][2];
                #pragma unroll
                for (int mi = 0; mi < 4; ++mi)
                    ldsm4(a[mi], stg + (a_row + mi*16)*80u + (uint32_t)ks*32u + a_kb);
                #pragma unroll
                for (int nip = 0; nip < 2; ++nip){
                    uint32_t r4[4];
                    ldsm4(r4, stgB + (b_row + nip*16)*80u + (uint32_t)ks*32u + b_kb);
                    b[nip*2  ][0] = r4[0]; b[nip*2  ][1] = r4[1];
                    b[nip*2+1][0] = r4[2]; b[nip*2+1][1] = r4[3];
                }
                #pragma unroll
                for (int ni = 0; ni < 4; ++ni)
                    #pragma unroll
                    for (int mi = 0; mi < 4; ++mi)
                        mma16816(acc[mi][ni], a[mi], b[ni][0], b[ni][1]);
            }
        }

        // ---- stage scores (offset bf16, bias folded) ----
        #pragma unroll
        for (int mi = 0; mi < 4; ++mi){
            const int row = wm*64 + mi*16 + g;
            #pragma unroll
            for (int ni = 0; ni < 4; ++ni){
                const int col = wn*32 + ni*8 + 2*tq;
                const float b0 = bias_s[col]     - SCOFF;
                const float b1 = bias_s[col + 1] - SCOFF;
                __nv_bfloat162* p0 =
                    (__nv_bfloat162*)(smem + SM_SC + ((size_t)row*SC_STRIDE + col)*2);
                __nv_bfloat162* p1 =
                    (__nv_bfloat162*)(smem + SM_SC + ((size_t)(row+8)*SC_STRIDE + col)*2);
                *p0 = __float22bfloat162_rn(
                        make_float2(acc[mi][ni][0] + b0, acc[mi][ni][1] + b1));
                *p1 = __float22bfloat162_rn(
                        make_float2(acc[mi][ni][2] + b0, acc[mi][ni][3] + b1));
            }
        }
        __syncthreads();

        // ---- per-(row,half) top-8 scan: threads 0..255, 2 per row ----
        if (tid < 256){
            const int row  = tid >> 1;
            const int half = tid & 1;
            const __nv_bfloat162* srow =
                (const __nv_bfloat162*)(smem + SM_SC + (size_t)row*SC_STRIDE*2) + half*64;
            const int base = tid * LDEPTH;
            const int n0   = nt * BN + half*128;
            #pragma unroll 4
            for (int j = 0; j < 64; ++j){
                const float2 f = __bfloat1622float2(srow[j]);
                if (f.x > thr){
                    int k = LDEPTH-1;
                    while (k > 0 && tsv_s[base+k-1] < f.x){
                        tsv_s[base+k] = tsv_s[base+k-1];
                        tsi_s[base+k] = tsi_s[base+k-1];
                        --k;
                    }
                    tsv_s[base+k] = f.x; tsi_s[base+k] = n0 + 2*j;
                    thr = tsv_s[base+LDEPTH-1];
                }
                if (f.y > thr){
                    int k = LDEPTH-1;
                    while (k > 0 && tsv_s[base+k-1] < f.y){
                        tsv_s[base+k] = tsv_s[base+k-1];
                        tsi_s[base+k] = tsi_s[base+k-1];
                        --k;
                    }
                    tsv_s[base+k] = f.y; tsi_s[base+k] = n0 + 2*j + 1;
                    thr = tsv_s[base+LDEPTH-1];
                }
            }
        }
        __syncthreads();
    }

    if (tid < 256){
        const int row  = tid >> 1;
        const int half = tid & 1;
        #pragma unroll
        for (int k = 0; k < LDEPTH; ++k)
            g_cand[(size_t)(row0 + row)*NCAND + half*LDEPTH + k] = tsi_s[tid*LDEPTH + k];
    }
}

// ---------------- kernel 3: exact rescore + softmax + combine ----------------
__global__ __launch_bounds__(256)
void rescore_kernel(const float* __restrict__ V,
                    const float* __restrict__ W,
                    const float* __restrict__ bias,
                    const float* __restrict__ pool,
                    float* __restrict__ out)
{
    const int lane = threadIdx.x & 31;
    const int wid  = threadIdx.x >> 5;
    const int row  = blockIdx.x * 8 + wid;

    int ids[NCAND]; float acc[NCAND];
    #pragma unroll
    for (int k = 0; k < NCAND; ++k){
        ids[k] = g_cand[(size_t)row*NCAND + k];
        acc[k] = 0.0f;
    }
    const float* vrow = V + (size_t)row * DIM;
    #pragma unroll 1
    for (int i = 0; i < DIM/32; ++i){
        const int d = i*32 + lane;
        const float v = vrow[d];
        #pragma unroll
        for (int k = 0; k < NCAND; ++k)
            acc[k] = fmaf(v, __ldg(&W[(size_t)ids[k]*DIM + d]), acc[k]);
    }
    #pragma unroll
    for (int k = 0; k < NCAND; ++k){
        #pragma unroll
        for (int off = 16; off; off >>= 1)
            acc[k] += __shfl_xor_sync(0xffffffffu, acc[k], off);
        acc[k] += bias[ids[k]];
    }
    #pragma unroll
    for (int a = 0; a < NCAND; ++a)
        #pragma unroll
        for (int j = 0; j < NCAND-1; ++j)
            if (acc[j] < acc[j+1]){
                float tv = acc[j]; acc[j] = acc[j+1]; acc[j+1] = tv;
                int   tx = ids[j]; ids[j] = ids[j+1]; ids[j+1] = tx;
            }
    const float m = acc[0];
    float e0 = expf(acc[0]-m), e1 = expf(acc[1]-m), e2 = expf(acc[2]-m),
          e3 = expf(acc[3]-m), e4 = expf(acc[4]-m);
    const float inv = 1.0f / (e0+e1+e2+e3+e4);
    e0 *= inv; e1 *= inv; e2 *= inv; e3 *= inv; e4 *= inv;
    const float* p0 = pool + (size_t)ids[0]*DIM;
    const float* p1 = pool + (size_t)ids[1]*DIM;
    const float* p2 = pool + (size_t)ids[2]*DIM;
    const float* p3 = pool + (size_t)ids[3]*DIM;
    const float* p4 = pool + (size_t)ids[4]*DIM;
    float* orow = out + (size_t)row * DIM;
    #pragma unroll 1
    for (int i = 0; i < DIM/32; ++i){
        const int d = i*32 + lane;
        float o = e0 * p0[d];
        o = fmaf(e1, p1[d], o);
        o = fmaf(e2, p2[d], o);
        o = fmaf(e3, p3[d], o);
        o = fmaf(e4, p4[d], o);
        orow[d] = o;
    }
}

// ---------------- launch ----------------
extern "C" void kernel_launch(void* const* d_in, const int* in_sizes, int n_in,
                              void* d_out, int out_size)
{
    const float* V    = (const float*)d_in[0];
    const float* W    = (const float*)d_in[1];
    const float* bias = (const float*)d_in[2];
    const float* pool = (const float*)d_in[3];
    float* out = (float*)d_out;

    cudaFuncSetAttribute(gemm_topk_kernel,
                         cudaFuncAttributeMaxDynamicSharedMemorySize, SM_TOTAL);

    convert_kernel<<<1184, 256>>>(V, W);
    gemm_topk_kernel<<<B_ROWS / BM, NTHREADS, SM_TOTAL>>>(bias);
    rescore_kernel<<<B_ROWS / 8, 256>>>(V, W, bias, pool, out);
}